// round 9
// baseline (speedup 1.0000x reference)
#include <cuda_runtime.h>

#define NFEAT 64
#define MAX_GRAPHS 16384

// seg_start[g] = first row i with idx[i] >= g. (+1 sentinel entry)
__device__ int g_seg_start[MAX_GRAPHS + 1];

// Vectorized boundary finder: each thread owns 4 consecutive idx values.
__global__ void bounds_kernel(const int* __restrict__ idx, int n, int num_graphs) {
    int t = blockIdx.x * blockDim.x + threadIdx.x;
    int base = t * 4;
    if (base >= n) return;

    int prev = (base > 0) ? __ldg(idx + base - 1) : -1;

    int vals[4];
    if (base + 3 < n) {
        int4 v = __ldg(reinterpret_cast<const int4*>(idx) + t);
        vals[0] = v.x; vals[1] = v.y; vals[2] = v.z; vals[3] = v.w;
    } else {
        #pragma unroll
        for (int j = 0; j < 4; ++j)
            vals[j] = (base + j < n) ? __ldg(idx + base + j) : 0;
    }

    #pragma unroll
    for (int j = 0; j < 4; ++j) {
        int e = base + j;
        if (e >= n) break;
        int cur = vals[j];
        for (int g = prev + 1; g <= cur; ++g)
            g_seg_start[g] = e;
        if (e == n - 1)
            for (int g = cur + 1; g <= num_graphs; ++g)
                g_seg_start[g] = n;
        prev = cur;
    }
}

// out[g,f] = (sum_seg x*exp(x)) / (sum_seg exp(x)).
// ONE WARP PER GRAPH (4 graphs per 128-thread block). Each lane owns features
// (2*lane, 2*lane+1) for the whole segment: one LDG.64 per lane per row
// (256B/warp coalesced), ~122 sequential iterations -> unroll 8 reaches deep
// steady-state MLP. No cross-lane reduction exists at all: each warp divides
// and stores its 64 outputs directly. No smem, no syncthreads, ~30 regs.
__global__ __launch_bounds__(128, 16) void readout_kernel(
    const float* __restrict__ feat,
    float*       __restrict__ out)
{
    const int warp = threadIdx.x >> 5;
    const int lane = threadIdx.x & 31;
    const int g    = blockIdx.x * 4 + warp;

    const int start = __ldg(&g_seg_start[g]);
    const int end   = __ldg(&g_seg_start[g + 1]);

    float e0 = 0.f, e1 = 0.f;   // sum exp(x) for features 2*lane, 2*lane+1
    float w0 = 0.f, w1 = 0.f;   // sum x*exp(x)

    const float2* __restrict__ f2 = reinterpret_cast<const float2*>(feat);

    #pragma unroll 8
    for (int r = start; r < end; ++r) {
        float2 v = __ldcs(f2 + (size_t)r * (NFEAT / 2) + lane);
        float a = __expf(v.x);
        float b = __expf(v.y);
        e0 += a;        e1 += b;
        w0 += v.x * a;  w1 += v.y * b;
    }

    float2 res;
    res.x = (e0 != 0.f) ? (w0 / e0) : 0.f;
    res.y = (e1 != 0.f) ? (w1 / e1) : 0.f;
    reinterpret_cast<float2*>(out)[(size_t)g * (NFEAT / 2) + lane] = res;
}

extern "C" void kernel_launch(void* const* d_in, const int* in_sizes, int n_in,
                              void* d_out, int out_size) {
    const float* feat = (const float*)d_in[0];   // (N_atoms, 64) float32
    const int*   idx  = (const int*)d_in[1];     // (N_atoms,)    int32, sorted
    float*       out  = (float*)d_out;           // (G, 64)       float32

    const int n_atoms    = in_sizes[1];
    const int num_graphs = out_size / NFEAT;     // 16384, divisible by 4

    int bthreads = (n_atoms + 3) / 4;
    bounds_kernel<<<(bthreads + 255) / 256, 256>>>(idx, n_atoms, num_graphs);
    readout_kernel<<<num_graphs / 4, 128>>>(feat, out);
}

// round 10
// speedup vs baseline: 1.0240x; 1.0240x over previous
#include <cuda_runtime.h>

#define NFEAT 64
#define MAX_GRAPHS 16384

// seg_start[g] = first row i with idx[i] >= g. (+1 sentinel entry)
__device__ int g_seg_start[MAX_GRAPHS + 1];

// Vectorized boundary finder: each thread owns 4 consecutive idx values.
__global__ void bounds_kernel(const int* __restrict__ idx, int n, int num_graphs) {
    int t = blockIdx.x * blockDim.x + threadIdx.x;
    int base = t * 4;
    if (base >= n) return;

    int prev = (base > 0) ? __ldg(idx + base - 1) : -1;

    int vals[4];
    if (base + 3 < n) {
        int4 v = __ldg(reinterpret_cast<const int4*>(idx) + t);
        vals[0] = v.x; vals[1] = v.y; vals[2] = v.z; vals[3] = v.w;
    } else {
        #pragma unroll
        for (int j = 0; j < 4; ++j)
            vals[j] = (base + j < n) ? __ldg(idx + base + j) : 0;
    }

    #pragma unroll
    for (int j = 0; j < 4; ++j) {
        int e = base + j;
        if (e >= n) break;
        int cur = vals[j];
        for (int g = prev + 1; g <= cur; ++g)
            g_seg_start[g] = e;
        if (e == n - 1)
            for (int g = cur + 1; g <= num_graphs; ++g)
                g_seg_start[g] = n;
        prev = cur;
    }
}

// out[g,f] = (sum_seg x*exp(x)) / (sum_seg exp(x)).
// One block per graph, 4 warps. Each warp streams row PAIRS via one LDG.128
// per lane (512B/warp/instr): lanes 0-15 hold even row, 16-31 odd row, lane
// owns features 4*(l&15)..+3. Address math is a single base pointer with a
// constant stride (no per-iter 64-bit IMAD) and a down-counted trip count,
// keeping regs <=36 so 14 blocks/SM fit. Odd leftover row folds into the
// final 64-thread phase.
__global__ __launch_bounds__(128, 14) void readout_kernel(
    const float* __restrict__ feat,
    float*       __restrict__ out)
{
    const int g     = blockIdx.x;
    const int start = __ldg(&g_seg_start[g]);
    const int end   = __ldg(&g_seg_start[g + 1]);

    const int lane = threadIdx.x & 31;
    const int w    = threadIdx.x >> 5;   // warp 0..3

    float4 e_acc = make_float4(0.f, 0.f, 0.f, 0.f);
    float4 w_acc = make_float4(0.f, 0.f, 0.f, 0.f);

    // Row pairs; warp w takes pair indices w, w+4, w+8, ...
    const int npairs = (end - start) >> 1;
    int it = (npairs > w) ? ((npairs - w + 3) >> 2) : 0;

    const float4* __restrict__ p = reinterpret_cast<const float4*>(feat)
                                 + (size_t)(start + 2 * w) * (NFEAT / 4) + lane;

    #pragma unroll 4
    for (; it > 0; --it) {
        float4 v = __ldcs(p);
        float a = __expf(v.x), b = __expf(v.y);
        float c = __expf(v.z), d = __expf(v.w);
        e_acc.x += a;       e_acc.y += b;
        e_acc.z += c;       e_acc.w += d;
        w_acc.x += v.x * a; w_acc.y += v.y * b;
        w_acc.z += v.z * c; w_acc.w += v.w * d;
        p += 8 * (NFEAT / 4);            // advance 8 rows
    }

    // Fold lanes 16-31 (odd row of pair, same features) into lanes 0-15.
    const unsigned FULL = 0xffffffffu;
    e_acc.x += __shfl_down_sync(FULL, e_acc.x, 16);
    e_acc.y += __shfl_down_sync(FULL, e_acc.y, 16);
    e_acc.z += __shfl_down_sync(FULL, e_acc.z, 16);
    e_acc.w += __shfl_down_sync(FULL, e_acc.w, 16);
    w_acc.x += __shfl_down_sync(FULL, w_acc.x, 16);
    w_acc.y += __shfl_down_sync(FULL, w_acc.y, 16);
    w_acc.z += __shfl_down_sync(FULL, w_acc.z, 16);
    w_acc.w += __shfl_down_sync(FULL, w_acc.w, 16);

    __shared__ float4 s_e[4][16];
    __shared__ float4 s_w[4][16];
    if (lane < 16) {
        s_e[w][lane] = e_acc;
        s_w[w][lane] = w_acc;
    }
    __syncthreads();

    if (threadIdx.x < NFEAT) {
        const int f = threadIdx.x;
        const float* se = reinterpret_cast<const float*>(s_e);
        const float* sw = reinterpret_cast<const float*>(s_w);
        float d = se[0 * NFEAT + f] + se[1 * NFEAT + f] + se[2 * NFEAT + f] + se[3 * NFEAT + f];
        float n = sw[0 * NFEAT + f] + sw[1 * NFEAT + f] + sw[2 * NFEAT + f] + sw[3 * NFEAT + f];

        // Odd leftover row: one coalesced LDG.32 per thread.
        if ((end - start) & 1) {
            float x = __ldcs(feat + (size_t)(end - 1) * NFEAT + f);
            float e = __expf(x);
            d += e;
            n += x * e;
        }
        out[(size_t)g * NFEAT + f] = (d != 0.f) ? (n / d) : 0.f;
    }
}

extern "C" void kernel_launch(void* const* d_in, const int* in_sizes, int n_in,
                              void* d_out, int out_size) {
    const float* feat = (const float*)d_in[0];   // (N_atoms, 64) float32
    const int*   idx  = (const int*)d_in[1];     // (N_atoms,)    int32, sorted
    float*       out  = (float*)d_out;           // (G, 64)       float32

    const int n_atoms    = in_sizes[1];
    const int num_graphs = out_size / NFEAT;

    int bthreads = (n_atoms + 3) / 4;
    bounds_kernel<<<(bthreads + 255) / 256, 256>>>(idx, n_atoms, num_graphs);
    readout_kernel<<<num_graphs, 128>>>(feat, out);
}

// round 11
// speedup vs baseline: 1.0406x; 1.0163x over previous
#include <cuda_runtime.h>

#define NFEAT 64
#define MAX_GRAPHS 16384

// seg_start[g] = first row i with idx[i] >= g. (+1 sentinel entry)
__device__ int g_seg_start[MAX_GRAPHS + 1];

// Vectorized boundary finder: each thread owns 4 consecutive idx values.
__global__ void bounds_kernel(const int* __restrict__ idx, int n, int num_graphs) {
    int t = blockIdx.x * blockDim.x + threadIdx.x;
    int base = t * 4;
    if (base >= n) return;

    int prev = (base > 0) ? __ldg(idx + base - 1) : -1;

    int vals[4];
    if (base + 3 < n) {
        int4 v = __ldg(reinterpret_cast<const int4*>(idx) + t);
        vals[0] = v.x; vals[1] = v.y; vals[2] = v.z; vals[3] = v.w;
    } else {
        #pragma unroll
        for (int j = 0; j < 4; ++j)
            vals[j] = (base + j < n) ? __ldg(idx + base + j) : 0;
    }

    #pragma unroll
    for (int j = 0; j < 4; ++j) {
        int e = base + j;
        if (e >= n) break;
        int cur = vals[j];
        for (int g = prev + 1; g <= cur; ++g)
            g_seg_start[g] = e;
        if (e == n - 1)
            for (int g = cur + 1; g <= num_graphs; ++g)
                g_seg_start[g] = n;
        prev = cur;
    }
}

// out[g,f] = (sum_seg x*exp(x)) / (sum_seg exp(x)).
// One block per graph, 4 warps. Each warp streams row PAIRS via one LDG.128
// per lane (512B/warp/instr): lanes 0-15 hold even row, 16-31 odd row, lane
// owns features 4*(l&15)..+3. Address math is a single base pointer with a
// constant stride (no per-iter 64-bit IMAD) and a down-counted trip count,
// keeping regs <=36 so 14 blocks/SM fit. Odd leftover row folds into the
// final 64-thread phase.
__global__ __launch_bounds__(128, 14) void readout_kernel(
    const float* __restrict__ feat,
    float*       __restrict__ out)
{
    const int g     = blockIdx.x;
    const int start = __ldg(&g_seg_start[g]);
    const int end   = __ldg(&g_seg_start[g + 1]);

    const int lane = threadIdx.x & 31;
    const int w    = threadIdx.x >> 5;   // warp 0..3

    float4 e_acc = make_float4(0.f, 0.f, 0.f, 0.f);
    float4 w_acc = make_float4(0.f, 0.f, 0.f, 0.f);

    // Row pairs; warp w takes pair indices w, w+4, w+8, ...
    const int npairs = (end - start) >> 1;
    int it = (npairs > w) ? ((npairs - w + 3) >> 2) : 0;

    const float4* __restrict__ p = reinterpret_cast<const float4*>(feat)
                                 + (size_t)(start + 2 * w) * (NFEAT / 4) + lane;

    #pragma unroll 4
    for (; it > 0; --it) {
        float4 v = __ldcs(p);
        float a = __expf(v.x), b = __expf(v.y);
        float c = __expf(v.z), d = __expf(v.w);
        e_acc.x += a;       e_acc.y += b;
        e_acc.z += c;       e_acc.w += d;
        w_acc.x += v.x * a; w_acc.y += v.y * b;
        w_acc.z += v.z * c; w_acc.w += v.w * d;
        p += 8 * (NFEAT / 4);            // advance 8 rows
    }

    // Fold lanes 16-31 (odd row of pair, same features) into lanes 0-15.
    const unsigned FULL = 0xffffffffu;
    e_acc.x += __shfl_down_sync(FULL, e_acc.x, 16);
    e_acc.y += __shfl_down_sync(FULL, e_acc.y, 16);
    e_acc.z += __shfl_down_sync(FULL, e_acc.z, 16);
    e_acc.w += __shfl_down_sync(FULL, e_acc.w, 16);
    w_acc.x += __shfl_down_sync(FULL, w_acc.x, 16);
    w_acc.y += __shfl_down_sync(FULL, w_acc.y, 16);
    w_acc.z += __shfl_down_sync(FULL, w_acc.z, 16);
    w_acc.w += __shfl_down_sync(FULL, w_acc.w, 16);

    __shared__ float4 s_e[4][16];
    __shared__ float4 s_w[4][16];
    if (lane < 16) {
        s_e[w][lane] = e_acc;
        s_w[w][lane] = w_acc;
    }
    __syncthreads();

    if (threadIdx.x < NFEAT) {
        const int f = threadIdx.x;
        const float* se = reinterpret_cast<const float*>(s_e);
        const float* sw = reinterpret_cast<const float*>(s_w);
        float d = se[0 * NFEAT + f] + se[1 * NFEAT + f] + se[2 * NFEAT + f] + se[3 * NFEAT + f];
        float n = sw[0 * NFEAT + f] + sw[1 * NFEAT + f] + sw[2 * NFEAT + f] + sw[3 * NFEAT + f];

        // Odd leftover row: one coalesced LDG.32 per thread.
        if ((end - start) & 1) {
            float x = __ldcs(feat + (size_t)(end - 1) * NFEAT + f);
            float e = __expf(x);
            d += e;
            n += x * e;
        }
        out[(size_t)g * NFEAT + f] = (d != 0.f) ? (n / d) : 0.f;
    }
}

extern "C" void kernel_launch(void* const* d_in, const int* in_sizes, int n_in,
                              void* d_out, int out_size) {
    const float* feat = (const float*)d_in[0];   // (N_atoms, 64) float32
    const int*   idx  = (const int*)d_in[1];     // (N_atoms,)    int32, sorted
    float*       out  = (float*)d_out;           // (G, 64)       float32

    const int n_atoms    = in_sizes[1];
    const int num_graphs = out_size / NFEAT;

    int bthreads = (n_atoms + 3) / 4;
    bounds_kernel<<<(bthreads + 255) / 256, 256>>>(idx, n_atoms, num_graphs);
    readout_kernel<<<num_graphs, 128>>>(feat, out);
}